// round 8
// baseline (speedup 1.0000x reference)
#include <cuda_runtime.h>
#include <cuda_bf16.h>
#include <math.h>
#include <cstdint>

#define Bn 16
#define Cn 128
#define Ln 2048
#define RSQRTC 0.08838834764831845f   // 1/sqrt(128)
#define NKB 16                        // k-blocks of 128 (split-K partials)

// ---------------- device-global scratch (no allocation allowed) ----------------
__device__ float g_ps[Bn * Ln * NKB];
__device__ float g_Sinv[Bn * Ln];
__device__ __nv_bfloat16 g_V_h[Bn * Cn * Ln];   // [b][c][k] hi
__device__ __nv_bfloat16 g_V_l[Bn * Cn * Ln];   // lo

// ---------------- helpers ----------------
__device__ __forceinline__ uint32_t smem_u32(const void* p) {
    uint32_t a;
    asm("{ .reg .u64 t; cvta.to.shared.u64 t, %1; cvt.u32.u64 %0, t; }" : "=r"(a) : "l"(p));
    return a;
}
__device__ __forceinline__ void ldsm4(uint32_t* r, uint32_t addr) {
    asm volatile("ldmatrix.sync.aligned.m8n8.x4.shared.b16 {%0,%1,%2,%3}, [%4];"
        : "=r"(r[0]), "=r"(r[1]), "=r"(r[2]), "=r"(r[3]) : "r"(addr));
}
__device__ __forceinline__ void ldsm4t(uint32_t* r, uint32_t addr) {
    asm volatile("ldmatrix.sync.aligned.m8n8.x4.trans.shared.b16 {%0,%1,%2,%3}, [%4];"
        : "=r"(r[0]), "=r"(r[1]), "=r"(r[2]), "=r"(r[3]) : "r"(addr));
}
__device__ __forceinline__ void mma_bf16(float* d, const uint32_t* a, const uint32_t* b) {
    asm volatile(
        "mma.sync.aligned.m16n8k16.row.col.f32.bf16.bf16.f32 "
        "{%0,%1,%2,%3}, {%4,%5,%6,%7}, {%8,%9}, {%0,%1,%2,%3};"
        : "+f"(d[0]), "+f"(d[1]), "+f"(d[2]), "+f"(d[3])
        : "r"(a[0]), "r"(a[1]), "r"(a[2]), "r"(a[3]), "r"(b[0]), "r"(b[1]));
}
__device__ __forceinline__ void split_bf16(float x, __nv_bfloat16& h, __nv_bfloat16& l) {
    h = __float2bfloat16_rn(x);
    l = __float2bfloat16_rn(x - __bfloat162float(h));
}
// pack two (hi,lo) splits of (x,y) into hi-pair / lo-pair words
__device__ __forceinline__ void split2(float x, float y, uint32_t& hp, uint32_t& lp) {
    __nv_bfloat16 hx, lx, hy, ly;
    split_bf16(x, hx, lx); split_bf16(y, hy, ly);
    __nv_bfloat162 H = __halves2bfloat162(hx, hy), L = __halves2bfloat162(lx, ly);
    hp = *(uint32_t*)&H; lp = *(uint32_t*)&L;
}

// XOR swizzle, pitch 256B (16 groups of 16B) or 128B (8 groups)
__device__ __forceinline__ uint32_t swz256(int row, int g) {
    return (uint32_t)(row * 256 + ((g ^ (row & 7)) * 16));
}
__device__ __forceinline__ uint32_t swz128(int row, int g) {
    return (uint32_t)(row * 128 + ((g ^ (row & 7)) * 16));
}

#define CPA16(dst, src) asm volatile("cp.async.cg.shared.global [%0], [%1], 16;" :: "r"(dst), "l"(src))
#define CPC()  asm volatile("cp.async.commit_group;" ::: "memory")
#define CPW0() asm volatile("cp.async.wait_group 0;" ::: "memory")

// ---------------------------------------------------------------------------
// prep_v: convert V f32 -> bf16 hi/lo (layout unchanged)
// ---------------------------------------------------------------------------
__global__ __launch_bounds__(256) void prep_v(const float* __restrict__ V)
{
    size_t i = (size_t)blockIdx.x * 256 + threadIdx.x;  // float4 index
    float4 v = ((const float4*)V)[i];
    uint32_t h0, l0, h1, l1;
    split2(v.x, v.y, h0, l0);
    split2(v.z, v.w, h1, l1);
    uint2* ph = (uint2*)(g_V_h + i * 4);
    uint2* pl = (uint2*)(g_V_l + i * 4);
    *ph = make_uint2(h0, h1);
    *pl = make_uint2(l0, l1);
}

// ---------------------------------------------------------------------------
// K1: P[b,k,q] = exp(score*rsqrtC + logmask), mma.sync bf16 3-term split.
// Q,K read f32 straight from gmem [b][c][l]; tiles stored K-major [c][*] in
// smem (native layout, no transpose), fragments via ldmatrix.trans.
// Tile 128(k) x 64(q). 8 warps = 4(m) x 2(n).
// smem: lm[128]f | psum[64][4]f | Ah 32K | Al 32K | Bh 16K | Bl 16K
// ---------------------------------------------------------------------------
#define S1_TOTAL (2048 + 98304)

__global__ __launch_bounds__(256, 2) void k1_mma(
    const float* __restrict__ Q, const float* __restrict__ Kf,
    const float* __restrict__ mask, float* __restrict__ attn)
{
    extern __shared__ char sm[];
    float* lmS  = (float*)sm;              // 128 floats
    float* psum = (float*)(sm + 512);      // [64][4]
    char* Ah = sm + 2048;
    char* Al = Ah + 32768;
    char* Bh = Al + 32768;
    char* Bl = Bh + 16384;

    int t = threadIdx.x;
    int b = blockIdx.z, kb = blockIdx.y, qb = blockIdx.x;
    int k0 = kb * 128, q0 = qb * 64;

    const float* Kb = Kf + (size_t)b * Cn * Ln;   // [c][l]
    const float* Qb = Q  + (size_t)b * Cn * Ln;

    // stage A: K tile [c=128][k=128] f32 -> bf16 hi/lo, K-major smem
#pragma unroll
    for (int i = 0; i < 16; i++) {
        int idx = t + i * 256, c = idx >> 5, kf4 = idx & 31;
        float4 v = *(const float4*)(Kb + (size_t)c * Ln + k0 + kf4 * 4);
        uint32_t h0, l0, h1, l1;
        split2(v.x, v.y, h0, l0);
        split2(v.z, v.w, h1, l1);
        uint32_t off = swz256(c, kf4 >> 1) + (kf4 & 1) * 8;
        *(uint2*)(Ah + off) = make_uint2(h0, h1);
        *(uint2*)(Al + off) = make_uint2(l0, l1);
    }
    // stage B: Q tile [c=128][q=64]
#pragma unroll
    for (int i = 0; i < 8; i++) {
        int idx = t + i * 256, c = idx >> 4, qf4 = idx & 15;
        float4 v = *(const float4*)(Qb + (size_t)c * Ln + q0 + qf4 * 4);
        uint32_t h0, l0, h1, l1;
        split2(v.x, v.y, h0, l0);
        split2(v.z, v.w, h1, l1);
        uint32_t off = swz128(c, qf4 >> 1) + (qf4 & 1) * 8;
        *(uint2*)(Bh + off) = make_uint2(h0, h1);
        *(uint2*)(Bl + off) = make_uint2(l0, l1);
    }
    if (t < 128) lmS[t] = __logf(__ldg(mask + b * Ln + k0 + t) + 1e-6f);
    __syncthreads();

    int w = t >> 5, l = t & 31;
    int wm = w & 3, wn = w >> 2;
    int mb0 = wm * 32, nb0 = wn * 32;

    float acc[2][4][4];
#pragma unroll
    for (int mt = 0; mt < 2; mt++)
#pragma unroll
        for (int nt = 0; nt < 4; nt++)
#pragma unroll
            for (int e = 0; e < 4; e++) acc[mt][nt][e] = 0.f;

    uint32_t sAh = smem_u32(Ah), sAl = smem_u32(Al);
    uint32_t sBh = smem_u32(Bh), sBl = smem_u32(Bl);

    // A trans-fragment lane addressing: rows c via bit4, m-group via bit3
    int arowT = (l & 7) + ((l >> 4) & 1) * 8;
    int agsel = (l >> 3) & 1;
    // B trans-fragment (as in k3): rows c via bit3, q-group via bit4
    int brow = (l & 7) + ((l >> 3) & 1) * 8;
    int bgsel = (l >> 4) & 1;

#pragma unroll
    for (int seg = 0; seg < 3; seg++) {
        uint32_t aBase = (seg == 2) ? sAl : sAh;
        uint32_t bBase = (seg == 1) ? sBl : sBh;
#pragma unroll
        for (int ks = 0; ks < 8; ks++) {
            uint32_t afr[2][4];
#pragma unroll
            for (int mt = 0; mt < 2; mt++)
                ldsm4t(afr[mt], aBase + swz256(ks * 16 + arowT,
                                               wm * 4 + mt * 2 + agsel));
            uint32_t bf[2][4];
#pragma unroll
            for (int np = 0; np < 2; np++)
                ldsm4t(bf[np], bBase + swz128(ks * 16 + brow,
                                              wn * 4 + np * 2 + bgsel));
#pragma unroll
            for (int mt = 0; mt < 2; mt++)
#pragma unroll
                for (int nt = 0; nt < 4; nt++)
                    mma_bf16(acc[mt][nt], afr[mt], &bf[nt >> 1][(nt & 1) * 2]);
        }
    }

    // epilogue: exp, store P, per-q partial sums
    int lq = (l & 3) * 2;
    int lr = l >> 2;
    float qs[4][2];
#pragma unroll
    for (int nt = 0; nt < 4; nt++) { qs[nt][0] = 0.f; qs[nt][1] = 0.f; }

#pragma unroll
    for (int mt = 0; mt < 2; mt++) {
        int krow = mb0 + mt * 16 + lr;
        float lm0 = lmS[krow], lm1 = lmS[krow + 8];
#pragma unroll
        for (int nt = 0; nt < 4; nt++) {
            float e0 = __expf(fmaf(acc[mt][nt][0], RSQRTC, lm0));
            float e1 = __expf(fmaf(acc[mt][nt][1], RSQRTC, lm0));
            float e2 = __expf(fmaf(acc[mt][nt][2], RSQRTC, lm1));
            float e3 = __expf(fmaf(acc[mt][nt][3], RSQRTC, lm1));
            size_t base = ((size_t)b << 22) + (size_t)(k0 + krow) * Ln
                        + q0 + nb0 + nt * 8 + lq;
            *(float2*)(attn + base)          = make_float2(e0, e1);
            *(float2*)(attn + base + 8 * Ln) = make_float2(e2, e3);
            qs[nt][0] += e0 + e2;
            qs[nt][1] += e1 + e3;
        }
    }
#pragma unroll
    for (int nt = 0; nt < 4; nt++)
#pragma unroll
        for (int s = 4; s < 32; s <<= 1) {
            qs[nt][0] += __shfl_xor_sync(0xFFFFFFFFu, qs[nt][0], s);
            qs[nt][1] += __shfl_xor_sync(0xFFFFFFFFu, qs[nt][1], s);
        }
    if (l < 4) {
#pragma unroll
        for (int nt = 0; nt < 4; nt++) {
            int nl = nb0 + nt * 8 + l * 2;
            psum[(nl + 0) * 4 + wm] = qs[nt][0];
            psum[(nl + 1) * 4 + wm] = qs[nt][1];
        }
    }
    __syncthreads();
    if (t < 64) {
        float S = psum[t * 4 + 0] + psum[t * 4 + 1] + psum[t * 4 + 2] + psum[t * 4 + 3];
        g_ps[((size_t)(b * Ln + q0 + t)) * NKB + kb] = S;
    }
}

// ---------------------------------------------------------------------------
// K2: combine split-K partial sums -> 1/S per (b,q)
// ---------------------------------------------------------------------------
__global__ __launch_bounds__(256) void k_sinv()
{
    int i = blockIdx.x * 256 + threadIdx.x;
    float S = 0.f;
#pragma unroll
    for (int c = 0; c < NKB; c++) S += g_ps[(size_t)i * NKB + c];
    g_Sinv[i] = 1.f / S;
}

// ---------------------------------------------------------------------------
// K3: w = P*Sinv*mask (written back as final attention); out = V @ w.
// Tile 128(c) x 64(q), 16 chunks of k=128. Pipelined:
//   V via cp.async (bf16 pre-split), P prefetched into regs under prev MMA.
// smem: Vh 32K | Vl 32K | Wh 16K | Wl 16K = 96K
// ---------------------------------------------------------------------------
#define S3_TOTAL 98304

__global__ __launch_bounds__(256, 2) void k3_mma(const float* __restrict__ mask,
                                                 float* __restrict__ attn,
                                                 float* __restrict__ out)
{
    extern __shared__ char sm[];
    char* Vh = sm;
    char* Vl = sm + 32768;
    char* Wh = sm + 65536;
    char* Wl = sm + 81920;

    int t = threadIdx.x;
    int b = blockIdx.y, q0 = blockIdx.x * 64;
    int w = t >> 5, l = t & 31;
    int wm = w & 3, wn = w >> 2;
    int mb0 = wm * 32, nb0 = wn * 32;

    float acc[2][4][4];
#pragma unroll
    for (int mt = 0; mt < 2; mt++)
#pragma unroll
        for (int nt = 0; nt < 4; nt++)
#pragma unroll
            for (int e = 0; e < 4; e++) acc[mt][nt][e] = 0.f;

    uint32_t sVh = smem_u32(Vh), sVl = smem_u32(Vl);
    uint32_t sWh = smem_u32(Wh), sWl = smem_u32(Wl);

    const uint4* vh = (const uint4*)(g_V_h + (size_t)b * Cn * Ln);
    const uint4* vl = (const uint4*)(g_V_l + (size_t)b * Cn * Ln);

    int q4  = t & 15;                      // float4 slot within 64 q
    int kr0 = t >> 4;                      // base k-row for staging
    float4 si = *(const float4*)(g_Sinv + (size_t)b * Ln + q0 + q4 * 4);

    int lrow8 = (l & 7) + ((l >> 3) & 1) * 8;
    int lgsel = (l >> 4) & 1;

    // V staging smem offsets/sources (row = idx>>4, g = idx&15)
    int vrow = t >> 4, vg = t & 15;

    // prefetch P chunk 0
    float4 pf[8];
#pragma unroll
    for (int i = 0; i < 8; i++) {
        int krow = kr0 + i * 16;
        pf[i] = *(const float4*)(attn + ((size_t)b << 22)
                 + (size_t)krow * Ln + q0 + q4 * 4);
    }

    for (int ch = 0; ch < 16; ch++) {
        int k0c = ch * 128;
        // issue V cp.async for this chunk (latency hides under P processing)
#pragma unroll
        for (int i = 0; i < 8; i++) {
            int row = vrow + i * 16;
            uint32_t off = swz256(row, vg);
            const uint4* sh = vh + (size_t)row * (Ln / 8) + k0c / 8 + vg;
            const uint4* sl = vl + (size_t)row * (Ln / 8) + k0c / 8 + vg;
            CPA16(sVh + off, sh);
            CPA16(sVl + off, sl);
        }
        CPC();

        // process prefetched P: normalize, write final attention, split to W
#pragma unroll
        for (int i = 0; i < 8; i++) {
            int krow = kr0 + i * 16;
            float4 p = pf[i];
            float mk = __ldg(mask + b * Ln + k0c + krow);
            p.x *= si.x * mk; p.y *= si.y * mk; p.z *= si.z * mk; p.w *= si.w * mk;
            *(float4*)(attn + ((size_t)b << 22) + (size_t)(k0c + krow) * Ln
                       + q0 + q4 * 4) = p;          // final attention output
            uint32_t h0, l0, h1, l1;
            split2(p.x, p.y, h0, l0);
            split2(p.z, p.w, h1, l1);
            uint32_t off = swz128(krow, q4 >> 1) + (q4 & 1) * 8;
            *(uint2*)(Wh + off) = make_uint2(h0, h1);
            *(uint2*)(Wl + off) = make_uint2(l0, l1);
        }
        CPW0();
        __syncthreads();

        // prefetch P for next chunk — LDG latency hides under the MMA section
        if (ch < 15) {
#pragma unroll
            for (int i = 0; i < 8; i++) {
                int krow = kr0 + i * 16;
                pf[i] = *(const float4*)(attn + ((size_t)b << 22)
                         + (size_t)(k0c + 128 + krow) * Ln + q0 + q4 * 4);
            }
        }

#pragma unroll
        for (int seg = 0; seg < 3; seg++) {
            uint32_t aBase = (seg == 2) ? sVl : sVh;
            uint32_t bBase = (seg == 1) ? sWl : sWh;
#pragma unroll
            for (int ks = 0; ks < 8; ks++) {
                uint32_t afr[2][4];
#pragma unroll
                for (int mt = 0; mt < 2; mt++) {
                    int row = mb0 + mt * 16 + lrow8;
                    ldsm4(afr[mt], aBase + swz256(row, ks * 2 + lgsel));
                }
                uint32_t bf[2][4];
#pragma unroll
                for (int np = 0; np < 2; np++) {
                    int row = ks * 16 + lrow8;
                    int qg  = wn * 4 + np * 2 + lgsel;
                    ldsm4t(bf[np], bBase + swz128(row, qg));
                }
#pragma unroll
                for (int mt = 0; mt < 2; mt++)
#pragma unroll
                    for (int nt = 0; nt < 4; nt++)
                        mma_bf16(acc[mt][nt], afr[mt], &bf[nt >> 1][(nt & 1) * 2]);
            }
        }
        __syncthreads();
    }

    // epilogue: D[c][q] -> out
    int lq = (l & 3) * 2;
    int lr = l >> 2;
#pragma unroll
    for (int mt = 0; mt < 2; mt++) {
        int c0 = mb0 + mt * 16 + lr;
#pragma unroll
        for (int nt = 0; nt < 4; nt++) {
            int q = q0 + nb0 + nt * 8 + lq;
            float* dst = out + ((size_t)b * Cn + c0) * Ln + q;
            *(float2*)dst            = make_float2(acc[mt][nt][0], acc[mt][nt][1]);
            *(float2*)(dst + 8 * Ln) = make_float2(acc[mt][nt][2], acc[mt][nt][3]);
        }
    }
}

// ---------------------------------------------------------------------------
extern "C" void kernel_launch(void* const* d_in, const int* in_sizes, int n_in,
                              void* d_out, int out_size)
{
    const float* Q    = (const float*)d_in[0];
    const float* K    = (const float*)d_in[1];
    const float* V    = (const float*)d_in[2];
    const float* mask = (const float*)d_in[3];

    float* out  = (float*)d_out;                      // [B, C, L]
    float* attn = out + (size_t)Bn * Cn * Ln;         // [B, Lk, Lq] (transposed)

    cudaFuncSetAttribute(k1_mma, cudaFuncAttributeMaxDynamicSharedMemorySize, S1_TOTAL);
    cudaFuncSetAttribute(k3_mma, cudaFuncAttributeMaxDynamicSharedMemorySize, S3_TOTAL);

    prep_v<<<(Bn * Cn * Ln / 4) / 256, 256>>>(V);

    dim3 g1(Ln / 64, Ln / 128, Bn);
    k1_mma<<<g1, 256, S1_TOTAL>>>(Q, K, mask, attn);

    k_sinv<<<(Bn * Ln) / 256, 256>>>();

    dim3 g3(Ln / 64, Bn);
    k3_mma<<<g3, 256, S3_TOTAL>>>(mask, attn, out);
}

// round 9
// speedup vs baseline: 1.0673x; 1.0673x over previous
#include <cuda_runtime.h>
#include <cuda_bf16.h>
#include <math.h>
#include <cstdint>

#define Bn 16
#define Cn 128
#define Ln 2048
#define RSQRTC 0.08838834764831845f   // 1/sqrt(128)
#define NKB 16                        // k-blocks of 128 (split-K partials)

// ---------------- device-global scratch (no allocation allowed) ----------------
__device__ float g_ps[Bn * Ln * NKB];
__device__ float g_Sinv[Bn * Ln];
__device__ __nv_bfloat16 g_V_h[Bn * Cn * Ln];   // [b][c][k] hi
__device__ __nv_bfloat16 g_V_l[Bn * Cn * Ln];   // lo

// ---------------- helpers ----------------
__device__ __forceinline__ uint32_t smem_u32(const void* p) {
    uint32_t a;
    asm("{ .reg .u64 t; cvta.to.shared.u64 t, %1; cvt.u32.u64 %0, t; }" : "=r"(a) : "l"(p));
    return a;
}
__device__ __forceinline__ void ldsm4(uint32_t* r, uint32_t addr) {
    asm volatile("ldmatrix.sync.aligned.m8n8.x4.shared.b16 {%0,%1,%2,%3}, [%4];"
        : "=r"(r[0]), "=r"(r[1]), "=r"(r[2]), "=r"(r[3]) : "r"(addr));
}
__device__ __forceinline__ void ldsm4t(uint32_t* r, uint32_t addr) {
    asm volatile("ldmatrix.sync.aligned.m8n8.x4.trans.shared.b16 {%0,%1,%2,%3}, [%4];"
        : "=r"(r[0]), "=r"(r[1]), "=r"(r[2]), "=r"(r[3]) : "r"(addr));
}
__device__ __forceinline__ void mma_bf16(float* d, const uint32_t* a, const uint32_t* b) {
    asm volatile(
        "mma.sync.aligned.m16n8k16.row.col.f32.bf16.bf16.f32 "
        "{%0,%1,%2,%3}, {%4,%5,%6,%7}, {%8,%9}, {%0,%1,%2,%3};"
        : "+f"(d[0]), "+f"(d[1]), "+f"(d[2]), "+f"(d[3])
        : "r"(a[0]), "r"(a[1]), "r"(a[2]), "r"(a[3]), "r"(b[0]), "r"(b[1]));
}
__device__ __forceinline__ void split_bf16(float x, __nv_bfloat16& h, __nv_bfloat16& l) {
    h = __float2bfloat16_rn(x);
    l = __float2bfloat16_rn(x - __bfloat162float(h));
}
// pack two (hi,lo) splits of (x,y) into hi-pair / lo-pair words
__device__ __forceinline__ void split2(float x, float y, uint32_t& hp, uint32_t& lp) {
    __nv_bfloat16 hx, lx, hy, ly;
    split_bf16(x, hx, lx); split_bf16(y, hy, ly);
    __nv_bfloat162 H = __halves2bfloat162(hx, hy), L = __halves2bfloat162(lx, ly);
    hp = *(uint32_t*)&H; lp = *(uint32_t*)&L;
}

// XOR swizzle, pitch 256B (16 groups of 16B) or 128B (8 groups)
__device__ __forceinline__ uint32_t swz256(int row, int g) {
    return (uint32_t)(row * 256 + ((g ^ (row & 7)) * 16));
}
__device__ __forceinline__ uint32_t swz128(int row, int g) {
    return (uint32_t)(row * 128 + ((g ^ (row & 7)) * 16));
}

// ---------------------------------------------------------------------------
// prep_v: convert V f32 -> bf16 hi/lo (layout unchanged)
// ---------------------------------------------------------------------------
__global__ __launch_bounds__(256) void prep_v(const float* __restrict__ V)
{
    size_t i = (size_t)blockIdx.x * 256 + threadIdx.x;  // float4 index
    float4 v = ((const float4*)V)[i];
    uint32_t h0, l0, h1, l1;
    split2(v.x, v.y, h0, l0);
    split2(v.z, v.w, h1, l1);
    uint2* ph = (uint2*)(g_V_h + i * 4);
    uint2* pl = (uint2*)(g_V_l + i * 4);
    *ph = make_uint2(h0, h1);
    *pl = make_uint2(l0, l1);
}

// ---------------------------------------------------------------------------
// K1: P[b,k,q] = exp(score*rsqrtC + logmask), mma.sync bf16 3-term split.
// Q,K read f32 straight from gmem [b][c][l]; tiles stored K-major [c][*] in
// smem (native layout, no transpose), fragments via ldmatrix.trans.
// Tile 128(k) x 64(q). 8 warps = 4(m) x 2(n).
// smem: lm[128]f | psum[64][4]f | Ah 32K | Al 32K | Bh 16K | Bl 16K
// ---------------------------------------------------------------------------
#define S1_TOTAL (2048 + 98304)

__global__ __launch_bounds__(256, 2) void k1_mma(
    const float* __restrict__ Q, const float* __restrict__ Kf,
    const float* __restrict__ mask, float* __restrict__ attn)
{
    extern __shared__ char sm[];
    float* lmS  = (float*)sm;              // 128 floats
    float* psum = (float*)(sm + 512);      // [64][4]
    char* Ah = sm + 2048;
    char* Al = Ah + 32768;
    char* Bh = Al + 32768;
    char* Bl = Bh + 16384;

    int t = threadIdx.x;
    int b = blockIdx.z, kb = blockIdx.y, qb = blockIdx.x;
    int k0 = kb * 128, q0 = qb * 64;

    const float* Kb = Kf + (size_t)b * Cn * Ln;   // [c][l]
    const float* Qb = Q  + (size_t)b * Cn * Ln;

    // stage A: K tile [c=128][k=128] f32 -> bf16 hi/lo, K-major smem
#pragma unroll
    for (int i = 0; i < 16; i++) {
        int idx = t + i * 256, c = idx >> 5, kf4 = idx & 31;
        float4 v = *(const float4*)(Kb + (size_t)c * Ln + k0 + kf4 * 4);
        uint32_t h0, l0, h1, l1;
        split2(v.x, v.y, h0, l0);
        split2(v.z, v.w, h1, l1);
        uint32_t off = swz256(c, kf4 >> 1) + (kf4 & 1) * 8;
        *(uint2*)(Ah + off) = make_uint2(h0, h1);
        *(uint2*)(Al + off) = make_uint2(l0, l1);
    }
    // stage B: Q tile [c=128][q=64]
#pragma unroll
    for (int i = 0; i < 8; i++) {
        int idx = t + i * 256, c = idx >> 4, qf4 = idx & 15;
        float4 v = *(const float4*)(Qb + (size_t)c * Ln + q0 + qf4 * 4);
        uint32_t h0, l0, h1, l1;
        split2(v.x, v.y, h0, l0);
        split2(v.z, v.w, h1, l1);
        uint32_t off = swz128(c, qf4 >> 1) + (qf4 & 1) * 8;
        *(uint2*)(Bh + off) = make_uint2(h0, h1);
        *(uint2*)(Bl + off) = make_uint2(l0, l1);
    }
    if (t < 128) lmS[t] = __logf(__ldg(mask + b * Ln + k0 + t) + 1e-6f);
    __syncthreads();

    int w = t >> 5, l = t & 31;
    int wm = w & 3, wn = w >> 2;
    int mb0 = wm * 32, nb0 = wn * 32;

    float acc[2][4][4];
#pragma unroll
    for (int mt = 0; mt < 2; mt++)
#pragma unroll
        for (int nt = 0; nt < 4; nt++)
#pragma unroll
            for (int e = 0; e < 4; e++) acc[mt][nt][e] = 0.f;

    uint32_t sAh = smem_u32(Ah), sAl = smem_u32(Al);
    uint32_t sBh = smem_u32(Bh), sBl = smem_u32(Bl);

    // A trans-fragment lane addressing: rows c via bit4, m-group via bit3
    int arowT = (l & 7) + ((l >> 4) & 1) * 8;
    int agsel = (l >> 3) & 1;
    // B trans-fragment: rows c via bit3, q-group via bit4
    int brow = (l & 7) + ((l >> 3) & 1) * 8;
    int bgsel = (l >> 4) & 1;

#pragma unroll
    for (int seg = 0; seg < 3; seg++) {
        uint32_t aBase = (seg == 2) ? sAl : sAh;
        uint32_t bBase = (seg == 1) ? sBl : sBh;
#pragma unroll
        for (int ks = 0; ks < 8; ks++) {
            uint32_t afr[2][4];
#pragma unroll
            for (int mt = 0; mt < 2; mt++)
                ldsm4t(afr[mt], aBase + swz256(ks * 16 + arowT,
                                               wm * 4 + mt * 2 + agsel));
            uint32_t bf[2][4];
#pragma unroll
            for (int np = 0; np < 2; np++)
                ldsm4t(bf[np], bBase + swz128(ks * 16 + brow,
                                              wn * 4 + np * 2 + bgsel));
#pragma unroll
            for (int mt = 0; mt < 2; mt++)
#pragma unroll
                for (int nt = 0; nt < 4; nt++)
                    mma_bf16(acc[mt][nt], afr[mt], &bf[nt >> 1][(nt & 1) * 2]);
        }
    }

    // epilogue: exp, store P, per-q partial sums
    int lq = (l & 3) * 2;
    int lr = l >> 2;
    float qs[4][2];
#pragma unroll
    for (int nt = 0; nt < 4; nt++) { qs[nt][0] = 0.f; qs[nt][1] = 0.f; }

#pragma unroll
    for (int mt = 0; mt < 2; mt++) {
        int krow = mb0 + mt * 16 + lr;
        float lm0 = lmS[krow], lm1 = lmS[krow + 8];
#pragma unroll
        for (int nt = 0; nt < 4; nt++) {
            float e0 = __expf(fmaf(acc[mt][nt][0], RSQRTC, lm0));
            float e1 = __expf(fmaf(acc[mt][nt][1], RSQRTC, lm0));
            float e2 = __expf(fmaf(acc[mt][nt][2], RSQRTC, lm1));
            float e3 = __expf(fmaf(acc[mt][nt][3], RSQRTC, lm1));
            size_t base = ((size_t)b << 22) + (size_t)(k0 + krow) * Ln
                        + q0 + nb0 + nt * 8 + lq;
            *(float2*)(attn + base)          = make_float2(e0, e1);
            *(float2*)(attn + base + 8 * Ln) = make_float2(e2, e3);
            qs[nt][0] += e0 + e2;
            qs[nt][1] += e1 + e3;
        }
    }
#pragma unroll
    for (int nt = 0; nt < 4; nt++)
#pragma unroll
        for (int s = 4; s < 32; s <<= 1) {
            qs[nt][0] += __shfl_xor_sync(0xFFFFFFFFu, qs[nt][0], s);
            qs[nt][1] += __shfl_xor_sync(0xFFFFFFFFu, qs[nt][1], s);
        }
    if (l < 4) {
#pragma unroll
        for (int nt = 0; nt < 4; nt++) {
            int nl = nb0 + nt * 8 + l * 2;
            psum[(nl + 0) * 4 + wm] = qs[nt][0];
            psum[(nl + 1) * 4 + wm] = qs[nt][1];
        }
    }
    __syncthreads();
    if (t < 64) {
        float S = psum[t * 4 + 0] + psum[t * 4 + 1] + psum[t * 4 + 2] + psum[t * 4 + 3];
        g_ps[((size_t)(b * Ln + q0 + t)) * NKB + kb] = S;
    }
}

// ---------------------------------------------------------------------------
// K2: combine split-K partial sums -> 1/S per (b,q)
// ---------------------------------------------------------------------------
__global__ __launch_bounds__(256) void k_sinv()
{
    int i = blockIdx.x * 256 + threadIdx.x;
    float S = 0.f;
#pragma unroll
    for (int c = 0; c < NKB; c++) S += g_ps[(size_t)i * NKB + c];
    g_Sinv[i] = 1.f / S;
}

// ---------------------------------------------------------------------------
// K3 (round-5 proven version): w = P*Sinv*mask (written back as final
// attention); out = V @ w. Tile 128(c) x 64(q), 16 chunks of k=128.
// A=V [c][k] via ldsm; B=w [k][q] via ldsm.trans. 8 warps = 4(m) x 2(n).
// smem: Vh 32K | Vl 32K | Wh 16K | Wl 16K = 96K
// ---------------------------------------------------------------------------
#define S3_TOTAL 98304

__global__ __launch_bounds__(256, 2) void k3_mma(const float* __restrict__ mask,
                                                 float* __restrict__ attn,
                                                 float* __restrict__ out)
{
    extern __shared__ char sm[];
    char* Vh = sm;
    char* Vl = sm + 32768;
    char* Wh = sm + 65536;
    char* Wl = sm + 81920;

    int t = threadIdx.x;
    int b = blockIdx.y, q0 = blockIdx.x * 64;
    int w = t >> 5, l = t & 31;
    int wm = w & 3, wn = w >> 2;
    int mb0 = wm * 32, nb0 = wn * 32;

    float acc[2][4][4];
#pragma unroll
    for (int mt = 0; mt < 2; mt++)
#pragma unroll
        for (int nt = 0; nt < 4; nt++)
#pragma unroll
            for (int e = 0; e < 4; e++) acc[mt][nt][e] = 0.f;

    uint32_t sVh = smem_u32(Vh), sVl = smem_u32(Vl);
    uint32_t sWh = smem_u32(Wh), sWl = smem_u32(Wl);

    const uint4* vh = (const uint4*)(g_V_h + (size_t)b * Cn * Ln);
    const uint4* vl = (const uint4*)(g_V_l + (size_t)b * Cn * Ln);

    int q4  = t & 15;                      // float4 slot within 64 q
    int kr0 = t >> 4;                      // base k-row for staging
    float4 si = *(const float4*)(g_Sinv + (size_t)b * Ln + q0 + q4 * 4);

    int lrow8 = (l & 7) + ((l >> 3) & 1) * 8;
    int lgsel = (l >> 4) & 1;

    for (int ch = 0; ch < 16; ch++) {
        int k0c = ch * 128;
        // stage V chunk: rows c=128, 16 groups of 16B (=128 k bf16)
#pragma unroll
        for (int i = 0; i < 8; i++) {
            int idx = t + i * 256, row = idx >> 4, g = idx & 15;
            uint32_t off = swz256(row, g);
            *(uint4*)(Vh + off) = vh[(size_t)row * (Ln / 8) + k0c / 8 + g];
            *(uint4*)(Vl + off) = vl[(size_t)row * (Ln / 8) + k0c / 8 + g];
        }
        // stage w: normalize P, write back final attention, bf16 hi/lo to smem
#pragma unroll
        for (int i = 0; i < 8; i++) {
            int krow = kr0 + i * 16;
            size_t aidx = ((size_t)b << 22) + (size_t)(k0c + krow) * Ln + q0 + q4 * 4;
            float4 p = *(float4*)(attn + aidx);
            float mk = __ldg(mask + b * Ln + k0c + krow);
            p.x *= si.x * mk; p.y *= si.y * mk; p.z *= si.z * mk; p.w *= si.w * mk;
            *(float4*)(attn + aidx) = p;     // final attention output
            uint32_t h0, l0, h1, l1;
            split2(p.x, p.y, h0, l0);
            split2(p.z, p.w, h1, l1);
            uint32_t off = swz128(krow, q4 >> 1) + (q4 & 1) * 8;
            *(uint2*)(Wh + off) = make_uint2(h0, h1);
            *(uint2*)(Wl + off) = make_uint2(l0, l1);
        }
        __syncthreads();

#pragma unroll
        for (int seg = 0; seg < 3; seg++) {
            uint32_t aBase = (seg == 2) ? sVl : sVh;
            uint32_t bBase = (seg == 1) ? sWl : sWh;
#pragma unroll
            for (int ks = 0; ks < 8; ks++) {
                uint32_t afr[2][4];
#pragma unroll
                for (int mt = 0; mt < 2; mt++) {
                    int row = mb0 + mt * 16 + lrow8;
                    ldsm4(afr[mt], aBase + swz256(row, ks * 2 + lgsel));
                }
                uint32_t bf[2][4];
#pragma unroll
                for (int np = 0; np < 2; np++) {
                    int row = ks * 16 + lrow8;
                    int qg  = wn * 4 + np * 2 + lgsel;
                    ldsm4t(bf[np], bBase + swz128(row, qg));
                }
#pragma unroll
                for (int mt = 0; mt < 2; mt++)
#pragma unroll
                    for (int nt = 0; nt < 4; nt++)
                        mma_bf16(acc[mt][nt], afr[mt], &bf[nt >> 1][(nt & 1) * 2]);
            }
        }
        __syncthreads();
    }

    // epilogue: D[c][q] -> out
    int lq = (l & 3) * 2;
    int lr = l >> 2;
#pragma unroll
    for (int mt = 0; mt < 2; mt++) {
        int c0 = mb0 + mt * 16 + lr;
#pragma unroll
        for (int nt = 0; nt < 4; nt++) {
            int q = q0 + nb0 + nt * 8 + lq;
            float* dst = out + ((size_t)b * Cn + c0) * Ln + q;
            *(float2*)dst            = make_float2(acc[mt][nt][0], acc[mt][nt][1]);
            *(float2*)(dst + 8 * Ln) = make_float2(acc[mt][nt][2], acc[mt][nt][3]);
        }
    }
}

// ---------------------------------------------------------------------------
extern "C" void kernel_launch(void* const* d_in, const int* in_sizes, int n_in,
                              void* d_out, int out_size)
{
    const float* Q    = (const float*)d_in[0];
    const float* K    = (const float*)d_in[1];
    const float* V    = (const float*)d_in[2];
    const float* mask = (const float*)d_in[3];

    float* out  = (float*)d_out;                      // [B, C, L]
    float* attn = out + (size_t)Bn * Cn * Ln;         // [B, Lk, Lq] (transposed)

    cudaFuncSetAttribute(k1_mma, cudaFuncAttributeMaxDynamicSharedMemorySize, S1_TOTAL);
    cudaFuncSetAttribute(k3_mma, cudaFuncAttributeMaxDynamicSharedMemorySize, S3_TOTAL);

    prep_v<<<(Bn * Cn * Ln / 4) / 256, 256>>>(V);

    dim3 g1(Ln / 64, Ln / 128, Bn);
    k1_mma<<<g1, 256, S1_TOTAL>>>(Q, K, mask, attn);

    k_sinv<<<(Bn * Ln) / 256, 256>>>();

    dim3 g3(Ln / 64, Bn);
    k3_mma<<<g3, 256, S3_TOTAL>>>(mask, attn, out);
}

// round 10
// speedup vs baseline: 1.2134x; 1.1369x over previous
#include <cuda_runtime.h>
#include <cuda_bf16.h>
#include <math.h>
#include <cstdint>

#define Bn 16
#define Cn 128
#define Ln 2048
#define RSQRTC 0.08838834764831845f   // 1/sqrt(128)
#define NKB 16                        // k-blocks of 128 (split-K partials)

// ---------------- device-global scratch (no allocation allowed) ----------------
__device__ float g_ps[Bn * Ln * NKB];
__device__ float g_Sinv[Bn * Ln];
__device__ __nv_bfloat16 g_Qh[Bn * Cn * Ln];    // [b][c][l] hi
__device__ __nv_bfloat16 g_Ql[Bn * Cn * Ln];
__device__ __nv_bfloat16 g_Kh[Bn * Cn * Ln];
__device__ __nv_bfloat16 g_Kl[Bn * Cn * Ln];
__device__ __nv_bfloat16 g_Vh[Bn * Cn * Ln];    // mask-folded V
__device__ __nv_bfloat16 g_Vl[Bn * Cn * Ln];
__device__ __nv_bfloat16 g_Ph[(size_t)Bn * Ln * Ln];  // unnormalized P hi
__device__ __nv_bfloat16 g_Pl[(size_t)Bn * Ln * Ln];  // lo

// ---------------- helpers ----------------
__device__ __forceinline__ uint32_t smem_u32(const void* p) {
    uint32_t a;
    asm("{ .reg .u64 t; cvta.to.shared.u64 t, %1; cvt.u32.u64 %0, t; }" : "=r"(a) : "l"(p));
    return a;
}
__device__ __forceinline__ void ldsm4(uint32_t* r, uint32_t addr) {
    asm volatile("ldmatrix.sync.aligned.m8n8.x4.shared.b16 {%0,%1,%2,%3}, [%4];"
        : "=r"(r[0]), "=r"(r[1]), "=r"(r[2]), "=r"(r[3]) : "r"(addr));
}
__device__ __forceinline__ void ldsm4t(uint32_t* r, uint32_t addr) {
    asm volatile("ldmatrix.sync.aligned.m8n8.x4.trans.shared.b16 {%0,%1,%2,%3}, [%4];"
        : "=r"(r[0]), "=r"(r[1]), "=r"(r[2]), "=r"(r[3]) : "r"(addr));
}
__device__ __forceinline__ void mma_bf16(float* d, const uint32_t* a, const uint32_t* b) {
    asm volatile(
        "mma.sync.aligned.m16n8k16.row.col.f32.bf16.bf16.f32 "
        "{%0,%1,%2,%3}, {%4,%5,%6,%7}, {%8,%9}, {%0,%1,%2,%3};"
        : "+f"(d[0]), "+f"(d[1]), "+f"(d[2]), "+f"(d[3])
        : "r"(a[0]), "r"(a[1]), "r"(a[2]), "r"(a[3]), "r"(b[0]), "r"(b[1]));
}
__device__ __forceinline__ void split_bf16(float x, __nv_bfloat16& h, __nv_bfloat16& l) {
    h = __float2bfloat16_rn(x);
    l = __float2bfloat16_rn(x - __bfloat162float(h));
}
__device__ __forceinline__ void split2(float x, float y, uint32_t& hp, uint32_t& lp) {
    __nv_bfloat16 hx, lx, hy, ly;
    split_bf16(x, hx, lx); split_bf16(y, hy, ly);
    __nv_bfloat162 H = __halves2bfloat162(hx, hy), L = __halves2bfloat162(lx, ly);
    hp = *(uint32_t*)&H; lp = *(uint32_t*)&L;
}
__device__ __forceinline__ uint32_t swz256(int row, int g) {
    return (uint32_t)(row * 256 + ((g ^ (row & 7)) * 16));
}
__device__ __forceinline__ uint32_t swz128(int row, int g) {
    return (uint32_t)(row * 128 + ((g ^ (row & 7)) * 16));
}

#define CPA16(dst, src) asm volatile("cp.async.cg.shared.global [%0], [%1], 16;" :: "r"(dst), "l"(src))
#define CPC()  asm volatile("cp.async.commit_group;" ::: "memory")
#define CPW0() asm volatile("cp.async.wait_group 0;" ::: "memory")
#define CPW1() asm volatile("cp.async.wait_group 1;" ::: "memory")

// ---------------------------------------------------------------------------
// prep_all: convert Q,K,V f32 -> bf16 hi/lo. V gets mask folded (Vm = V*mask[k]).
// blockIdx.y selects tensor: 0=Q, 1=K, 2=V.
// ---------------------------------------------------------------------------
__global__ __launch_bounds__(256) void prep_all(
    const float* __restrict__ Q, const float* __restrict__ K,
    const float* __restrict__ V, const float* __restrict__ mask)
{
    int which = blockIdx.y;
    const float* src = (which == 0) ? Q : (which == 1) ? K : V;
    __nv_bfloat16* dh = (which == 0) ? g_Qh : (which == 1) ? g_Kh : g_Vh;
    __nv_bfloat16* dl = (which == 0) ? g_Ql : (which == 1) ? g_Kl : g_Vl;

    size_t i = (size_t)blockIdx.x * 256 + threadIdx.x;  // float4 idx
    float4 v = ((const float4*)src)[i];
    if (which == 2) {
        size_t e = i * 4;
        int b = (int)(e >> 18);            // Cn*Ln = 2^18
        int k = (int)(e & (Ln - 1));
        float4 mk = *(const float4*)(mask + b * Ln + k);
        v.x *= mk.x; v.y *= mk.y; v.z *= mk.z; v.w *= mk.w;
    }
    uint32_t h0, l0, h1, l1;
    split2(v.x, v.y, h0, l0);
    split2(v.z, v.w, h1, l1);
    *(uint2*)(dh + i * 4) = make_uint2(h0, h1);
    *(uint2*)(dl + i * 4) = make_uint2(l0, l1);
}

// ---------------------------------------------------------------------------
// K1: P = exp(score*rsqrtC + logmask) -> bf16 hi/lo to g_Ph/g_Pl,
// plus split-K partial sums. Operands pre-converted, staged via cp.async.
// Tile 128(k) x 64(q), Kdim=c=128. 8 warps = 4(m) x 2(n).
// smem: lm[128]f | psum[64][4]f | Ah 32K | Al 32K | Bh 16K | Bl 16K
// ---------------------------------------------------------------------------
#define S1_TOTAL (2048 + 98304)

__global__ __launch_bounds__(256, 2) void k1_mma(
    const float* __restrict__ mask)
{
    extern __shared__ char sm[];
    float* lmS  = (float*)sm;              // 128 floats
    float* psum = (float*)(sm + 512);      // [64][4]
    uint32_t sAh = smem_u32(sm + 2048);
    uint32_t sAl = sAh + 32768;
    uint32_t sBh = sAl + 32768;
    uint32_t sBl = sBh + 16384;

    int t = threadIdx.x;
    int b = blockIdx.z, kb = blockIdx.y, qb = blockIdx.x;
    int k0 = kb * 128, q0 = qb * 64;
    size_t cb = (size_t)b * Cn * Ln;

    // stage A = K tile [c=128][k=128] hi/lo via cp.async
#pragma unroll
    for (int i = 0; i < 8; i++) {
        int idx = t + i * 256, c = idx >> 4, g = idx & 15;
        uint32_t off = swz256(c, g);
        const __nv_bfloat16* s = g_Kh + cb + (size_t)c * Ln + k0 + g * 8;
        CPA16(sAh + off, s);
        CPA16(sAl + off, g_Kl + cb + (size_t)c * Ln + k0 + g * 8);
    }
    // stage B = Q tile [c=128][q=64]
#pragma unroll
    for (int i = 0; i < 4; i++) {
        int idx = t + i * 256, c = idx >> 3, g = idx & 7;
        uint32_t off = swz128(c, g);
        CPA16(sBh + off, g_Qh + cb + (size_t)c * Ln + q0 + g * 8);
        CPA16(sBl + off, g_Ql + cb + (size_t)c * Ln + q0 + g * 8);
    }
    CPC();
    if (t < 128) lmS[t] = __logf(__ldg(mask + b * Ln + k0 + t) + 1e-6f);
    CPW0();
    __syncthreads();

    int w = t >> 5, l = t & 31;
    int wm = w & 3, wn = w >> 2;
    int mb0 = wm * 32, nb0 = wn * 32;

    float acc[2][4][4];
#pragma unroll
    for (int mt = 0; mt < 2; mt++)
#pragma unroll
        for (int nt = 0; nt < 4; nt++)
#pragma unroll
            for (int e = 0; e < 4; e++) acc[mt][nt][e] = 0.f;

    // A trans-fragment: rows c via bit4, m-group via bit3
    int arowT = (l & 7) + ((l >> 4) & 1) * 8;
    int agsel = (l >> 3) & 1;
    // B trans-fragment: rows c via bit3, q-group via bit4
    int brow = (l & 7) + ((l >> 3) & 1) * 8;
    int bgsel = (l >> 4) & 1;

#pragma unroll
    for (int seg = 0; seg < 3; seg++) {
        uint32_t aBase = (seg == 2) ? sAl : sAh;
        uint32_t bBase = (seg == 1) ? sBl : sBh;
#pragma unroll
        for (int ks = 0; ks < 8; ks++) {
            uint32_t afr[2][4];
#pragma unroll
            for (int mt = 0; mt < 2; mt++)
                ldsm4t(afr[mt], aBase + swz256(ks * 16 + arowT,
                                               wm * 4 + mt * 2 + agsel));
            uint32_t bf[2][4];
#pragma unroll
            for (int np = 0; np < 2; np++)
                ldsm4t(bf[np], bBase + swz128(ks * 16 + brow,
                                              wn * 4 + np * 2 + bgsel));
#pragma unroll
            for (int mt = 0; mt < 2; mt++)
#pragma unroll
                for (int nt = 0; nt < 4; nt++)
                    mma_bf16(acc[mt][nt], afr[mt], &bf[nt >> 1][(nt & 1) * 2]);
        }
    }

    // epilogue: exp, store P (bf16 hi/lo), per-q partial sums
    int lq = (l & 3) * 2;
    int lr = l >> 2;
    float qs[4][2];
#pragma unroll
    for (int nt = 0; nt < 4; nt++) { qs[nt][0] = 0.f; qs[nt][1] = 0.f; }

#pragma unroll
    for (int mt = 0; mt < 2; mt++) {
        int krow = mb0 + mt * 16 + lr;
        float lm0 = lmS[krow], lm1 = lmS[krow + 8];
#pragma unroll
        for (int nt = 0; nt < 4; nt++) {
            float e0 = __expf(fmaf(acc[mt][nt][0], RSQRTC, lm0));
            float e1 = __expf(fmaf(acc[mt][nt][1], RSQRTC, lm0));
            float e2 = __expf(fmaf(acc[mt][nt][2], RSQRTC, lm1));
            float e3 = __expf(fmaf(acc[mt][nt][3], RSQRTC, lm1));
            size_t base = ((size_t)b << 22) + (size_t)(k0 + krow) * Ln
                        + q0 + nb0 + nt * 8 + lq;
            uint32_t hp, lp;
            split2(e0, e1, hp, lp);
            *(uint32_t*)(g_Ph + base) = hp;
            *(uint32_t*)(g_Pl + base) = lp;
            split2(e2, e3, hp, lp);
            *(uint32_t*)(g_Ph + base + 8 * Ln) = hp;
            *(uint32_t*)(g_Pl + base + 8 * Ln) = lp;
            qs[nt][0] += e0 + e2;
            qs[nt][1] += e1 + e3;
        }
    }
#pragma unroll
    for (int nt = 0; nt < 4; nt++)
#pragma unroll
        for (int s = 4; s < 32; s <<= 1) {
            qs[nt][0] += __shfl_xor_sync(0xFFFFFFFFu, qs[nt][0], s);
            qs[nt][1] += __shfl_xor_sync(0xFFFFFFFFu, qs[nt][1], s);
        }
    if (l < 4) {
#pragma unroll
        for (int nt = 0; nt < 4; nt++) {
            int nl = nb0 + nt * 8 + l * 2;
            psum[(nl + 0) * 4 + wm] = qs[nt][0];
            psum[(nl + 1) * 4 + wm] = qs[nt][1];
        }
    }
    __syncthreads();
    if (t < 64) {
        float S = psum[t * 4 + 0] + psum[t * 4 + 1] + psum[t * 4 + 2] + psum[t * 4 + 3];
        g_ps[((size_t)(b * Ln + q0 + t)) * NKB + kb] = S;
    }
}

// ---------------------------------------------------------------------------
// K2: combine split-K partial sums -> 1/S per (b,q)
// ---------------------------------------------------------------------------
__global__ __launch_bounds__(256) void k_sinv()
{
    int i = blockIdx.x * 256 + threadIdx.x;
    float S = 0.f;
#pragma unroll
    for (int c = 0; c < NKB; c++) S += g_ps[(size_t)i * NKB + c];
    g_Sinv[i] = 1.f / S;
}

// ---------------------------------------------------------------------------
// k_norm: pure streaming — w = (Ph+Pl)*Sinv[q]*mask[k] -> f32 attention output
// ---------------------------------------------------------------------------
__global__ __launch_bounds__(256) void k_norm(const float* __restrict__ mask,
                                              float* __restrict__ attn)
{
    size_t e = ((size_t)blockIdx.x * 256 + threadIdx.x) * 8;
    int b = (int)(e >> 22);
    int k = (int)((e >> 11) & (Ln - 1));
    int q = (int)(e & (Ln - 1));

    uint4 ph = *(const uint4*)(g_Ph + e);
    uint4 pl = *(const uint4*)(g_Pl + e);
    float4 s0 = *(const float4*)(g_Sinv + b * Ln + q);
    float4 s1 = *(const float4*)(g_Sinv + b * Ln + q + 4);
    float mk = __ldg(mask + b * Ln + k);

    const __nv_bfloat162* hp = (const __nv_bfloat162*)&ph;
    const __nv_bfloat162* lp = (const __nv_bfloat162*)&pl;
    float p[8];
#pragma unroll
    for (int i = 0; i < 4; i++) {
        p[2 * i]     = __bfloat162float(hp[i].x) + __bfloat162float(lp[i].x);
        p[2 * i + 1] = __bfloat162float(hp[i].y) + __bfloat162float(lp[i].y);
    }
    *(float4*)(attn + e) = make_float4(p[0] * s0.x * mk, p[1] * s0.y * mk,
                                       p[2] * s0.z * mk, p[3] * s0.w * mk);
    *(float4*)(attn + e + 4) = make_float4(p[4] * s1.x * mk, p[5] * s1.y * mk,
                                           p[6] * s1.z * mk, p[7] * s1.w * mk);
}

// ---------------------------------------------------------------------------
// k3_gemm: out[b,c,q] = (Vm @ P) * Sinv[q]. Pure double-buffered GEMM.
// Tile 128(c) x 64(q), 32 chunks of k=64, cp.async 2-stage pipeline.
// smem per stage: Vh 16K | Vl 16K | Ph 8K | Pl 8K = 48K; x2 = 96K.
// ---------------------------------------------------------------------------
#define G_STAGE 49152
#define G_VH 0
#define G_VL 16384
#define G_PH 32768
#define G_PL 40960
#define S3_TOTAL (2 * G_STAGE)

__global__ __launch_bounds__(256, 2) void k3_gemm(float* __restrict__ out)
{
    extern __shared__ char sm[];
    uint32_t sb = smem_u32(sm);

    int t = threadIdx.x;
    int b = blockIdx.y, q0 = blockIdx.x * 64;
    int w = t >> 5, l = t & 31;
    int wm = w & 3, wn = w >> 2;
    int mb0 = wm * 32, nb0 = wn * 32;
    size_t vb = (size_t)b * Cn * Ln;
    size_t pb = (size_t)b << 22;

    float acc[2][4][4];
#pragma unroll
    for (int mt = 0; mt < 2; mt++)
#pragma unroll
        for (int nt = 0; nt < 4; nt++)
#pragma unroll
            for (int e = 0; e < 4; e++) acc[mt][nt][e] = 0.f;

    int lrow8 = (l & 7) + ((l >> 3) & 1) * 8;
    int lgsel = (l >> 4) & 1;

    // staging thread roles
    int vc = t >> 3, vg = t & 7;           // V: 2 iters cover 128 rows? (see loop)
    // V: 128 rows x 8 groups = 1024 uint4 -> 4 iters of 256
    // P: 64 rows x 8 groups = 512 uint4 -> 2 iters of 256

#define STAGE(ch, bufi) do {                                                   \
    uint32_t base = sb + (bufi) * G_STAGE;                                     \
    int k0c = (ch) * 64;                                                       \
    _Pragma("unroll")                                                          \
    for (int i = 0; i < 4; i++) {                                              \
        int idx = t + i * 256, c = idx >> 3, g = idx & 7;                      \
        uint32_t off = swz128(c, g);                                           \
        CPA16(base + G_VH + off, g_Vh + vb + (size_t)c * Ln + k0c + g * 8);    \
        CPA16(base + G_VL + off, g_Vl + vb + (size_t)c * Ln + k0c + g * 8);    \
    }                                                                          \
    _Pragma("unroll")                                                          \
    for (int i = 0; i < 2; i++) {                                              \
        int idx = t + i * 256, k = idx >> 3, g = idx & 7;                      \
        uint32_t off = swz128(k, g);                                           \
        CPA16(base + G_PH + off, g_Ph + pb + (size_t)(k0c + k) * Ln + q0 + g * 8); \
        CPA16(base + G_PL + off, g_Pl + pb + (size_t)(k0c + k) * Ln + q0 + g * 8); \
    }                                                                          \
    CPC();                                                                     \
} while (0)

    STAGE(0, 0);

    for (int ch = 0; ch < 32; ch++) {
        int bi = ch & 1;
        if (ch < 31) STAGE(ch + 1, bi ^ 1);
        if (ch < 31) { CPW1(); } else { CPW0(); }
        __syncthreads();

        uint32_t base = sb + bi * G_STAGE;
#pragma unroll
        for (int seg = 0; seg < 3; seg++) {
            uint32_t aBase = base + ((seg == 2) ? G_VL : G_VH);
            uint32_t bBase = base + ((seg == 1) ? G_PL : G_PH);
#pragma unroll
            for (int ks = 0; ks < 4; ks++) {
                uint32_t afr[2][4];
#pragma unroll
                for (int mt = 0; mt < 2; mt++) {
                    int row = mb0 + mt * 16 + lrow8;
                    ldsm4(afr[mt], aBase + swz128(row, ks * 2 + lgsel));
                }
                uint32_t bf[2][4];
#pragma unroll
                for (int np = 0; np < 2; np++) {
                    int row = ks * 16 + lrow8;
                    int qg  = wn * 4 + np * 2 + lgsel;
                    ldsm4t(bf[np], bBase + swz128(row, qg));
                }
#pragma unroll
                for (int mt = 0; mt < 2; mt++)
#pragma unroll
                    for (int nt = 0; nt < 4; nt++)
                        mma_bf16(acc[mt][nt], afr[mt], &bf[nt >> 1][(nt & 1) * 2]);
            }
        }
        __syncthreads();
    }

    // epilogue: scale by Sinv[q], write out
    int lq = (l & 3) * 2;
    int lr = l >> 2;
#pragma unroll
    for (int mt = 0; mt < 2; mt++) {
        int c0 = mb0 + mt * 16 + lr;
#pragma unroll
        for (int nt = 0; nt < 4; nt++) {
            int q = q0 + nb0 + nt * 8 + lq;
            float si0 = __ldg(g_Sinv + b * Ln + q);
            float si1 = __ldg(g_Sinv + b * Ln + q + 1);
            float* dst = out + ((size_t)b * Cn + c0) * Ln + q;
            *(float2*)dst = make_float2(acc[mt][nt][0] * si0, acc[mt][nt][1] * si1);
            *(float2*)(dst + 8 * Ln) =
                make_float2(acc[mt][nt][2] * si0, acc[mt][nt][3] * si1);
        }
    }
}

// ---------------------------------------------------------------------------
extern "C" void kernel_launch(void* const* d_in, const int* in_sizes, int n_in,
                              void* d_out, int out_size)
{
    const float* Q    = (const float*)d_in[0];
    const float* K    = (const float*)d_in[1];
    const float* V    = (const float*)d_in[2];
    const float* mask = (const float*)d_in[3];

    float* out  = (float*)d_out;                      // [B, C, L]
    float* attn = out + (size_t)Bn * Cn * Ln;         // [B, Lk, Lq] (transposed)

    cudaFuncSetAttribute(k1_mma, cudaFuncAttributeMaxDynamicSharedMemorySize, S1_TOTAL);
    cudaFuncSetAttribute(k3_gemm, cudaFuncAttributeMaxDynamicSharedMemorySize, S3_TOTAL);

    dim3 gp((Bn * Cn * Ln / 4) / 256, 3);
    prep_all<<<gp, 256>>>(Q, K, V, mask);

    dim3 g1(Ln / 64, Ln / 128, Bn);
    k1_mma<<<g1, 256, S1_TOTAL>>>(mask);

    k_sinv<<<(Bn * Ln) / 256, 256>>>();

    k_norm<<<((size_t)Bn * Ln * Ln / 8) / 256, 256>>>(mask, attn);

    dim3 g3(Ln / 64, Bn);
    k3_gemm<<<g3, 256, S3_TOTAL>>>(out);
}